// round 14
// baseline (speedup 1.0000x reference)
#include <cuda_runtime.h>
#include <cuda_fp16.h>
#include <cstdint>

#define B_DIM 32
#define C_DIM 512
#define N_DIM 1024   // H*W

// ---------------- device scratch (allocation-free) --------------------------
__device__ __align__(16) unsigned short g_wv[64 * 512];     // Wv^T fp16 [d][c]
__device__ __align__(16) unsigned short g_wp[512 * 512];    // Wp^T fp16 [c2][c]
__device__ float g_bv[64];
__device__ __align__(16) unsigned g_v[B_DIM * 1024 * 32];   // v fp16 pairs [b][n][d/2]
__device__ int g_flag[B_DIM];                               // per-batch producer count

// ---------------- helpers ----------------------------------------------------
__device__ __forceinline__ unsigned smem_u32(const void* p) {
    unsigned a;
    asm("{ .reg .u64 t; cvta.to.shared.u64 t, %1; cvt.u32.u64 %0, t; }" : "=r"(a) : "l"(p));
    return a;
}
__device__ __forceinline__ void ldm_x4(unsigned* d, unsigned addr) {
    asm volatile("ldmatrix.sync.aligned.m8n8.x4.shared.b16 {%0,%1,%2,%3}, [%4];"
                 : "=r"(d[0]), "=r"(d[1]), "=r"(d[2]), "=r"(d[3]) : "r"(addr));
}
__device__ __forceinline__ void mma_f16(float* c, const unsigned* a, const unsigned* b) {
    asm volatile(
        "mma.sync.aligned.m16n8k16.row.col.f32.f16.f16.f32 "
        "{%0,%1,%2,%3}, {%4,%5,%6,%7}, {%8,%9}, {%0,%1,%2,%3};"
        : "+f"(c[0]), "+f"(c[1]), "+f"(c[2]), "+f"(c[3])
        : "r"(a[0]), "r"(a[1]), "r"(a[2]), "r"(a[3]), "r"(b[0]), "r"(b[1]));
}
__device__ __forceinline__ void cp16(unsigned dst, const void* src) {
    asm volatile("cp.async.cg.shared.global [%0], [%1], 16;" :: "r"(dst), "l"(src));
}
__device__ __forceinline__ void cp_commit() { asm volatile("cp.async.commit_group;" ::: "memory"); }
__device__ __forceinline__ void cp_wait0()  { asm volatile("cp.async.wait_group 0;" ::: "memory"); }

__device__ __forceinline__ unsigned cvt_f16x2(float f0, float f1) {
    unsigned h;
    asm("cvt.rn.f16x2.f32 %0, %1, %2;" : "=r"(h) : "f"(f1), "f"(f0));
    return h;
}

// smem layout (both phases):
//   [0, 66560)            B-full: 64 rows x 512 halves, pitch 1040 B
//   [66560, 66560+2*18432) A stages: 128 rows x 64 halves, pitch 144 B
// gemm2 epilogue Cs [64][132] floats (33792 B) reuses the A-stage region.
#define BPITCH 1040
#define A_OFF  66560
#define A_STG  18432
#define FUSED_SMEM (A_OFF + 2 * A_STG)   // 103424 -> 2 CTAs/SM

// ---------------------------------------------------------------------------
// prep (separate launch): blocks [0,128) -> Wv^T fp16 + bias; [128,384) -> Wp^T
// Zeroes per-batch flags each replay.
// ---------------------------------------------------------------------------
__global__ void prep_all(const float* __restrict__ Wqkv, const float* __restrict__ bqkv,
                         const float* __restrict__ Wp) {
    int bid = blockIdx.x, tid = threadIdx.x;
    if (bid == 0 && tid < B_DIM) g_flag[tid] = 0;
    if (bid < 128) {
        int idx = bid * 256 + tid;                 // 32768
        int d = idx & 63, c = idx >> 6;
        const float* p = Wqkv + (size_t)c * 1536 + 1024 + d;
        float s = 0.f;
        #pragma unroll
        for (int h = 0; h < 8; ++h) s += p[h * 64];
        s *= 0.125f;
        __half hv = __float2half_rn(s);
        g_wv[d * 512 + c] = *(unsigned short*)&hv;
        if (idx < 64) {
            float t = 0.f;
            #pragma unroll
            for (int h = 0; h < 8; ++h) t += bqkv[1024 + h * 64 + idx];
            g_bv[idx] = t * 0.125f;
        }
    } else {
        __shared__ float ts[32][33];
        int t = bid - 128;                          // 256 tiles
        int c0 = (t & 15) * 32, c20 = (t >> 4) * 32;
        int tx = tid & 31, ty = tid >> 5;           // (32, 8)
        #pragma unroll
        for (int i = 0; i < 4; ++i) {
            int c = c0 + ty + i * 8;
            ts[ty + i * 8][tx] = Wp[(size_t)c * 512 + c20 + tx];
        }
        __syncthreads();
        #pragma unroll
        for (int i = 0; i < 4; ++i) {
            int c2 = c20 + ty + i * 8;
            __half hb = __float2half_rn(ts[tx][ty + i * 8]);
            g_wp[(size_t)c2 * 512 + c0 + tx] = *(unsigned short*)&hb;
        }
    }
}

// ---------------- warp MMA fragment offsets ----------------------------------
struct Frag { unsigned aoff[2]; unsigned boff[2]; };

__device__ __forceinline__ Frag make_frag(int lane, int mw, int nw) {
    Frag fr;
    const int j4 = lane >> 3, r8 = lane & 7;
    #pragma unroll
    for (int mi = 0; mi < 2; ++mi)   // A rows in stage (pitch 144)
        fr.aoff[mi] = A_OFF + (mw * 32 + mi * 16 + (j4 & 1) * 8 + r8) * 144 + (j4 >> 1) * 16;
    const int g2 = (lane >> 4) & 1, c8 = (lane >> 3) & 1;
    #pragma unroll
    for (int j2 = 0; j2 < 2; ++j2)   // B rows in resident region (pitch 1040)
        fr.boff[j2] = (nw * 32 + j2 * 16 + g2 * 8 + r8) * BPITCH + c8 * 16;
    return fr;
}

// A from stage (kc-independent), B from resident region at byte offset kc*128
template<int K0, int K1>
__device__ __forceinline__ void mma_stage(unsigned sbA, unsigned sbB_kc,
                                          const Frag& fr, float C[2][4][4]) {
    #pragma unroll
    for (int ks = K0; ks < K1; ++ks) {
        unsigned a[2][4], b[2][4];
        #pragma unroll
        for (int mi = 0; mi < 2; ++mi)
            ldm_x4(a[mi], sbA + fr.aoff[mi] + ks * 32);
        #pragma unroll
        for (int j2 = 0; j2 < 2; ++j2)
            ldm_x4(b[j2], sbB_kc + fr.boff[j2] + ks * 32);
        #pragma unroll
        for (int mi = 0; mi < 2; ++mi)
            #pragma unroll
            for (int ni = 0; ni < 4; ++ni)
                mma_f16(C[mi][ni], a[mi], &b[ni >> 1][(ni & 1) * 2]);
    }
}

// copy full 64x512-half B into resident region (one cp.async group, no commit)
__device__ __forceinline__ void copyB_full(unsigned sb, const unsigned short* src, int tid) {
    #pragma unroll
    for (int i = 0; i < 16; ++i) {
        int idx = tid + i * 256;                   // 4096 quads: 64 rows x 64
        int r = idx >> 6, q = idx & 63;
        cp16(sb + r * BPITCH + q * 16, src + (size_t)r * 512 + q * 8);
    }
}

// -------------------- GEMM1 body: tile 128(n) x 64(d), K-chunk 64 x 8 -------
__device__ __forceinline__ void gemm1_body(const float* __restrict__ x,
                                           char* smem, int b, int n0) {
    const int tid = threadIdx.x, lane = tid & 31, wid = tid >> 5;
    const int mw = wid >> 1, nw = wid & 1;
    const unsigned sb = smem_u32(smem);
    const Frag fr = make_frag(lane, mw, nw);

    const int m_ld = tid & 127, kb0 = tid >> 7;
    const float* xb = x + (size_t)b * (C_DIM * N_DIM) + n0;

    float C[2][4][4] = {};
    float f[2][8];

    auto ldg_half = [&](int kc, int h) {
        const float* xc = xb + (size_t)(kc * 64 + h * 32) * N_DIM;
        #pragma unroll
        for (int i = 0; i < 2; ++i) {
            int k0 = (kb0 + 2 * i) * 8;
            #pragma unroll
            for (int j = 0; j < 8; ++j)
                f[i][j] = xc[(size_t)(k0 + j) * N_DIM + m_ld];
        }
    };
    auto cvt_half = [&](int st, int h) {
        char* base = smem + A_OFF + st * A_STG;
        #pragma unroll
        for (int i = 0; i < 2; ++i) {
            unsigned w0 = cvt_f16x2(f[i][0], f[i][1]);
            unsigned w1 = cvt_f16x2(f[i][2], f[i][3]);
            unsigned w2 = cvt_f16x2(f[i][4], f[i][5]);
            unsigned w3 = cvt_f16x2(f[i][6], f[i][7]);
            unsigned off = m_ld * 144 + h * 64 + (kb0 + 2 * i) * 16;
            *(uint4*)(base + off) = make_uint4(w0, w1, w2, w3);
        }
    };

    // prologue: resident B copy first (overlaps everything), then stage 0
    copyB_full(sb, g_wv, tid);
    cp_commit();
    ldg_half(0, 0);
    cvt_half(0, 0);
    ldg_half(0, 1);
    cvt_half(0, 1);
    ldg_half(1, 0);
    cp_wait0();

    for (int kc = 0; kc < 8; ++kc) {
        const int st = kc & 1, nst = st ^ 1;
        __syncthreads();
        if (kc < 7) { cvt_half(nst, 0); ldg_half(kc + 1, 1); }
        mma_stage<0, 2>(sb + st * A_STG, sb + kc * 128, fr, C);
        if (kc < 7) { cvt_half(nst, 1); if (kc < 6) ldg_half(kc + 2, 0); }
        mma_stage<2, 4>(sb + st * A_STG, sb + kc * 128, fr, C);
    }

    // epilogue: add bias, convert to fp16, store v
    const int gr = lane >> 2, gc2 = (lane & 3) * 2;
    #pragma unroll
    for (int mi = 0; mi < 2; ++mi) {
        int m = n0 + mw * 32 + mi * 16 + gr;
        unsigned base0 = (unsigned)(b * 1024 + m) * 32u;
        unsigned base1 = base0 + 8 * 32;
        #pragma unroll
        for (int ni = 0; ni < 4; ++ni) {
            int d = nw * 32 + ni * 8 + gc2;
            float bv0 = g_bv[d], bv1 = g_bv[d + 1];
            g_v[base0 + (d >> 1)] = cvt_f16x2(C[mi][ni][0] + bv0, C[mi][ni][1] + bv1);
            g_v[base1 + (d >> 1)] = cvt_f16x2(C[mi][ni][2] + bv0, C[mi][ni][3] + bv1);
        }
    }

    __threadfence();
    __syncthreads();
    if (tid == 0) atomicAdd(&g_flag[b], 1);
}

// -------------------- GEMM2 body: tile 128(r) x 64(c2), K-chunk 64 x 8 ------
__device__ __forceinline__ void gemm2_body(const float* __restrict__ bp,
                                           float* __restrict__ out,
                                           char* smem, int b, int c20) {
    const int tid = threadIdx.x, lane = tid & 31, wid = tid >> 5;
    const int mw = wid >> 1, nw = wid & 1;
    const unsigned sb = smem_u32(smem);
    const Frag fr = make_frag(lane, mw, nw);

    // resident B (Wp rows c20..c20+63) — no dependency on v; overlaps the spin
    copyB_full(sb, g_wp + (size_t)c20 * 512, tid);
    cp_commit();

    // acquire: wait for all 8 producer CTAs of this batch
    if (tid == 0) {
        volatile int* fl = &g_flag[b];
        while (*fl < 8) __nanosleep(64);
    }
    __syncthreads();
    __threadfence();

    const unsigned short* vb = (const unsigned short*)g_v + (size_t)b * 65536;

    float C[2][4][4] = {};

    auto issueA = [&](int kc, int st) {
        unsigned stb = sb + A_OFF + st * A_STG;
        #pragma unroll
        for (int i = 0; i < 4; ++i) {
            int idx = tid + i * 256;               // 1024 quads: 128 rows x 8
            int r = idx >> 3, q = idx & 7;
            cp16(stb + r * 144 + q * 16, vb + (size_t)r * 512 + kc * 64 + q * 8);
        }
        cp_commit();
    };

    issueA(0, 0);
    cp_wait0();          // drains B-full + A chunk 0
    __syncthreads();

    for (int kc = 0; kc < 8; ++kc) {
        const int st = kc & 1;
        if (kc < 7) issueA(kc + 1, st ^ 1);
        mma_stage<0, 4>(sb + st * A_STG, sb + kc * 128, fr, C);
        if (kc < 7) { cp_wait0(); __syncthreads(); }
    }
    __syncthreads();

    // epilogue: stage to smem [c2][r] with bias, then coalesced x8 broadcast
    float* Cs = (float*)(smem + A_OFF);   // [64][132] floats = 33792 B <= 36864
    const int gr = lane >> 2, gc2 = (lane & 3) * 2;
    #pragma unroll
    for (int mi = 0; mi < 2; ++mi) {
        int r = mw * 32 + mi * 16 + gr;
        #pragma unroll
        for (int ni = 0; ni < 4; ++ni) {
            int c2l = nw * 32 + ni * 8 + gc2;
            float b0 = __ldg(bp + c20 + c2l), b1 = __ldg(bp + c20 + c2l + 1);
            Cs[c2l * 132 + r]           = C[mi][ni][0] + b0;
            Cs[(c2l + 1) * 132 + r]     = C[mi][ni][1] + b1;
            Cs[c2l * 132 + r + 8]       = C[mi][ni][2] + b0;
            Cs[(c2l + 1) * 132 + r + 8] = C[mi][ni][3] + b1;
        }
    }
    __syncthreads();

    float* ob = out + (size_t)b * (C_DIM * N_DIM) + (size_t)c20 * N_DIM;
    const int f4 = tid & 31, sub = tid >> 5;
    #pragma unroll 4
    for (int i = 0; i < 64; ++i) {
        int rowid = i * 8 + sub;                   // 512 row-writes
        int c2l = rowid >> 3, mrep = rowid & 7;
        float4 v = *(float4*)&Cs[c2l * 132 + f4 * 4];
        *(float4*)(ob + (size_t)c2l * N_DIM + mrep * 128 + f4 * 4) = v;
    }
}

// ---------------------------------------------------------------------------
// Persistent fused kernel: 256 CTAs x 256 threads, 2 CTAs/SM (all resident).
// CTA i: produce gemm1 tile (b=i>>3, n0=(i&7)*128), then consume gemm2 tile
// (b=i>>3, c20=(i&7)*64). Producers never wait -> deadlock-free.
// ---------------------------------------------------------------------------
__global__ void __launch_bounds__(256, 2) fused_mma(const float* __restrict__ x,
                                                    const float* __restrict__ bp,
                                                    float* __restrict__ out) {
    extern __shared__ char smem[];
    const int bid = blockIdx.x;
    const int b = bid >> 3, t8 = bid & 7;
    gemm1_body(x, smem, b, t8 * 128);
    gemm2_body(bp, out, smem, b, t8 * 64);
}

// ---------------------------------------------------------------------------
extern "C" void kernel_launch(void* const* d_in, const int* in_sizes, int n_in,
                              void* d_out, int out_size) {
    const float* x    = (const float*)d_in[0];
    const float* Wqkv = (const float*)d_in[1];
    const float* bqkv = (const float*)d_in[2];
    const float* Wp   = (const float*)d_in[3];
    const float* bp   = (const float*)d_in[4];
    float* out = (float*)d_out;

    cudaFuncSetAttribute(fused_mma, cudaFuncAttributeMaxDynamicSharedMemorySize, FUSED_SMEM);

    prep_all<<<384, 256>>>(Wqkv, bqkv, Wp);
    fused_mma<<<256, 256, FUSED_SMEM>>>(x, bp, out);
}

// round 15
// speedup vs baseline: 1.3020x; 1.3020x over previous
#include <cuda_runtime.h>
#include <cuda_fp16.h>
#include <cstdint>

#define B_DIM 32
#define C_DIM 512
#define N_DIM 1024   // H*W

// ---------------- device scratch (allocation-free) --------------------------
__device__ __align__(16) unsigned short g_wv[64 * 512];     // Wv^T fp16 [d][c]
__device__ __align__(16) unsigned short g_wp[512 * 512];    // Wp^T fp16 [c2][c]
__device__ float g_bv[64];
__device__ __align__(16) unsigned g_v[B_DIM * 1024 * 32];   // v fp16 pairs [b][n][d/2]
__device__ int g_flag[B_DIM];   // per-batch producer count (reset by prep_wv)
__device__ int g_wready;        // Wp-prep arrivals (reset by prep_wv)

// ---------------- helpers ----------------------------------------------------
__device__ __forceinline__ unsigned smem_u32(const void* p) {
    unsigned a;
    asm("{ .reg .u64 t; cvta.to.shared.u64 t, %1; cvt.u32.u64 %0, t; }" : "=r"(a) : "l"(p));
    return a;
}
__device__ __forceinline__ void ldm_x4(unsigned* d, unsigned addr) {
    asm volatile("ldmatrix.sync.aligned.m8n8.x4.shared.b16 {%0,%1,%2,%3}, [%4];"
                 : "=r"(d[0]), "=r"(d[1]), "=r"(d[2]), "=r"(d[3]) : "r"(addr));
}
__device__ __forceinline__ void mma_f16(float* c, const unsigned* a, const unsigned* b) {
    asm volatile(
        "mma.sync.aligned.m16n8k16.row.col.f32.f16.f16.f32 "
        "{%0,%1,%2,%3}, {%4,%5,%6,%7}, {%8,%9}, {%0,%1,%2,%3};"
        : "+f"(c[0]), "+f"(c[1]), "+f"(c[2]), "+f"(c[3])
        : "r"(a[0]), "r"(a[1]), "r"(a[2]), "r"(a[3]), "r"(b[0]), "r"(b[1]));
}
__device__ __forceinline__ void cp16(unsigned dst, const void* src) {
    asm volatile("cp.async.cg.shared.global [%0], [%1], 16;" :: "r"(dst), "l"(src));
}
__device__ __forceinline__ void cp_commit() { asm volatile("cp.async.commit_group;" ::: "memory"); }
__device__ __forceinline__ void cp_wait0()  { asm volatile("cp.async.wait_group 0;" ::: "memory"); }

__device__ __forceinline__ unsigned cvt_f16x2(float f0, float f1) {
    unsigned h;
    asm("cvt.rn.f16x2.f32 %0, %1, %2;" : "=r"(h) : "f"(f1), "f"(f0));
    return h;
}

// stage layout (pitch 144B): A[128 rows] @0 (18432) | B[64 rows] @18432 (9216)
#define H_B   18432
#define H_STG 27648
#define FUSED_SMEM (2 * H_STG)   // 55296 -> 2 CTAs/SM

// ---------------------------------------------------------------------------
// prep_wv (tiny separate launch): Wv^T fp16 + bias; resets flags for replay.
// ---------------------------------------------------------------------------
__global__ void prep_wv(const float* __restrict__ Wqkv, const float* __restrict__ bqkv) {
    int idx = blockIdx.x * 256 + threadIdx.x;      // 32768
    if (idx < B_DIM) g_flag[idx] = 0;
    if (idx == 32) g_wready = 0;
    int d = idx & 63, c = idx >> 6;
    const float* p = Wqkv + (size_t)c * 1536 + 1024 + d;
    float s = 0.f;
    #pragma unroll
    for (int h = 0; h < 8; ++h) s += p[h * 64];
    s *= 0.125f;
    __half hv = __float2half_rn(s);
    g_wv[d * 512 + c] = *(unsigned short*)&hv;
    if (idx >= 64 && idx < 128) {
        int j = idx - 64;
        float t = 0.f;
        #pragma unroll
        for (int h = 0; h < 8; ++h) t += bqkv[1024 + h * 64 + j];
        g_bv[j] = t * 0.125f;
    }
}

// ---------------- warp MMA fragment offsets (pitch 144B) ---------------------
struct Frag { unsigned aoff[2]; unsigned boff[2]; };

__device__ __forceinline__ Frag make_frag(int lane, int mw, int nw) {
    Frag fr;
    const int j4 = lane >> 3, r8 = lane & 7;
    #pragma unroll
    for (int mi = 0; mi < 2; ++mi)
        fr.aoff[mi] = (mw * 32 + mi * 16 + (j4 & 1) * 8 + r8) * 144 + (j4 >> 1) * 16;
    const int g2 = (lane >> 4) & 1, c8 = (lane >> 3) & 1;
    #pragma unroll
    for (int j2 = 0; j2 < 2; ++j2)
        fr.boff[j2] = H_B + (nw * 32 + j2 * 16 + g2 * 8 + r8) * 144 + c8 * 16;
    return fr;
}

template<int K0, int K1>
__device__ __forceinline__ void mma_stage(unsigned base, const Frag& fr, float C[2][4][4]) {
    #pragma unroll
    for (int ks = K0; ks < K1; ++ks) {
        unsigned a[2][4], b[2][4];
        #pragma unroll
        for (int mi = 0; mi < 2; ++mi)
            ldm_x4(a[mi], base + fr.aoff[mi] + ks * 32);
        #pragma unroll
        for (int j2 = 0; j2 < 2; ++j2)
            ldm_x4(b[j2], base + fr.boff[j2] + ks * 32);
        #pragma unroll
        for (int mi = 0; mi < 2; ++mi)
            #pragma unroll
            for (int ni = 0; ni < 4; ++ni)
                mma_f16(C[mi][ni], a[mi], &b[ni >> 1][(ni & 1) * 2]);
    }
}

// ---------------- Wp prep tile (head of fused kernel) ------------------------
__device__ __forceinline__ void prep_wp_tile(const float* __restrict__ Wp,
                                             char* smem, int bid, int tid) {
    float (*ts)[33] = (float(*)[33])smem;          // 4224 B scratch
    int c0 = (bid & 15) * 32, c20 = (bid >> 4) * 32;
    int tx = tid & 31, ty = tid >> 5;              // (32, 8)
    #pragma unroll
    for (int i = 0; i < 4; ++i) {
        int c = c0 + ty + i * 8;
        ts[ty + i * 8][tx] = Wp[(size_t)c * 512 + c20 + tx];
    }
    __syncthreads();
    #pragma unroll
    for (int i = 0; i < 4; ++i) {
        int c2 = c20 + ty + i * 8;
        __half hb = __float2half_rn(ts[tx][ty + i * 8]);
        g_wp[(size_t)c2 * 512 + c0 + tx] = *(unsigned short*)&hb;
    }
    __threadfence();
    __syncthreads();                               // protect ts before gemm1 reuses smem
    if (tid == 0) atomicAdd(&g_wready, 1);
}

// -------------------- GEMM1 body: tile 128(n) x 64(d), K-chunk 64 x 8 -------
__device__ __forceinline__ void gemm1_body(const float* __restrict__ x,
                                           char* smem, int b, int n0) {
    const int tid = threadIdx.x, lane = tid & 31, wid = tid >> 5;
    const int mw = wid >> 1, nw = wid & 1;
    const unsigned sb = smem_u32(smem);
    const Frag fr = make_frag(lane, mw, nw);

    const int m_ld = tid & 127, kb0 = tid >> 7;    // kblocks kb0 + 2i within half
    const float* xb = x + (size_t)b * (C_DIM * N_DIM) + n0;

    float C[2][4][4] = {};
    float f[2][8];

    auto ldg_half = [&](int kc, int h) {
        const float* xc = xb + (size_t)(kc * 64 + h * 32) * N_DIM;
        #pragma unroll
        for (int i = 0; i < 2; ++i) {
            int k0 = (kb0 + 2 * i) * 8;
            #pragma unroll
            for (int j = 0; j < 8; ++j)
                f[i][j] = xc[(size_t)(k0 + j) * N_DIM + m_ld];
        }
    };
    auto cvt_half = [&](int st, int h) {
        char* base = smem + st * H_STG;
        #pragma unroll
        for (int i = 0; i < 2; ++i) {
            unsigned w0 = cvt_f16x2(f[i][0], f[i][1]);
            unsigned w1 = cvt_f16x2(f[i][2], f[i][3]);
            unsigned w2 = cvt_f16x2(f[i][4], f[i][5]);
            unsigned w3 = cvt_f16x2(f[i][6], f[i][7]);
            unsigned off = m_ld * 144 + h * 64 + (kb0 + 2 * i) * 16;
            *(uint4*)(base + off) = make_uint4(w0, w1, w2, w3);
        }
    };
    auto issueB = [&](int kc, int st) {
        unsigned stb = sb + st * H_STG + H_B;
        #pragma unroll
        for (int i = 0; i < 2; ++i) {
            int idx = tid + i * 256;               // 512 quads: 64 rows x 8
            int r = idx >> 3, q = idx & 7;
            size_t s = (size_t)r * 512 + kc * 64 + q * 8;
            cp16(stb + r * 144 + q * 16, g_wv + s);
        }
        cp_commit();
    };

    // prologue: stage 0 = chunk 0 full; f = chunk 1 half 0
    ldg_half(0, 0);
    cvt_half(0, 0);
    ldg_half(0, 1);
    cvt_half(0, 1);
    ldg_half(1, 0);
    issueB(0, 0);

    for (int kc = 0; kc < 8; ++kc) {
        const int st = kc & 1, nst = st ^ 1;
        cp_wait0();
        __syncthreads();
        if (kc < 7) { cvt_half(nst, 0); issueB(kc + 1, nst); ldg_half(kc + 1, 1); }
        mma_stage<0, 2>(sb + st * H_STG, fr, C);
        if (kc < 7) { cvt_half(nst, 1); if (kc < 6) ldg_half(kc + 2, 0); }
        mma_stage<2, 4>(sb + st * H_STG, fr, C);
    }

    // epilogue: add bias, convert to fp16, store v
    const int gr = lane >> 2, gc2 = (lane & 3) * 2;
    #pragma unroll
    for (int mi = 0; mi < 2; ++mi) {
        int m = n0 + mw * 32 + mi * 16 + gr;
        unsigned base0 = (unsigned)(b * 1024 + m) * 32u;
        unsigned base1 = base0 + 8 * 32;
        #pragma unroll
        for (int ni = 0; ni < 4; ++ni) {
            int d = nw * 32 + ni * 8 + gc2;
            float bv0 = g_bv[d], bv1 = g_bv[d + 1];
            g_v[base0 + (d >> 1)] = cvt_f16x2(C[mi][ni][0] + bv0, C[mi][ni][1] + bv1);
            g_v[base1 + (d >> 1)] = cvt_f16x2(C[mi][ni][2] + bv0, C[mi][ni][3] + bv1);
        }
    }

    __threadfence();
    __syncthreads();
    if (tid == 0) atomicAdd(&g_flag[b], 1);
}

// -------------------- GEMM2 body: tile 128(r) x 64(c2), K-chunk 64 x 8 ------
__device__ __forceinline__ void gemm2_body(const float* __restrict__ bp,
                                           float* __restrict__ out,
                                           char* smem, int b, int c20) {
    const int tid = threadIdx.x, lane = tid & 31, wid = tid >> 5;
    const int mw = wid >> 1, nw = wid & 1;
    const unsigned sb = smem_u32(smem);
    const Frag fr = make_frag(lane, mw, nw);

    // acquire: Wp prep complete device-wide (long satisfied) + this batch's v
    if (tid == 0) {
        volatile int* w = &g_wready;
        while (*w < 256) __nanosleep(64);
        volatile int* fl = &g_flag[b];
        while (*fl < 8) __nanosleep(64);
    }
    __syncthreads();
    __threadfence();

    const unsigned short* vb = (const unsigned short*)g_v + (size_t)b * 65536;

    float C[2][4][4] = {};

    auto issue = [&](int kc, int st) {
        unsigned stb = sb + st * H_STG;
        #pragma unroll
        for (int i = 0; i < 4; ++i) {
            int idx = tid + i * 256;               // 1024 quads (A: 128 rows x 8)
            int r = idx >> 3, q = idx & 7;
            size_t s = (size_t)r * 512 + kc * 64 + q * 8;
            cp16(stb + r * 144 + q * 16, vb + s);
        }
        #pragma unroll
        for (int i = 0; i < 2; ++i) {
            int idx = tid + i * 256;               // 512 quads (B: 64 rows x 8)
            int r = idx >> 3, q = idx & 7;
            size_t s = (size_t)(c20 + r) * 512 + kc * 64 + q * 8;
            cp16(stb + H_B + r * 144 + q * 16, g_wp + s);
        }
        cp_commit();
    };

    issue(0, 0);

    for (int kc = 0; kc < 8; ++kc) {
        const int st = kc & 1;
        cp_wait0();
        __syncthreads();
        if (kc < 7) issue(kc + 1, st ^ 1);
        mma_stage<0, 4>(sb + st * H_STG, fr, C);
    }
    __syncthreads();

    // epilogue: stage to smem [c2][r] with bias, then coalesced x8 broadcast
    float* Cs = (float*)smem;      // [64][132] floats = 33792 B <= 55296
    const int gr = lane >> 2, gc2 = (lane & 3) * 2;
    #pragma unroll
    for (int mi = 0; mi < 2; ++mi) {
        int r = mw * 32 + mi * 16 + gr;
        #pragma unroll
        for (int ni = 0; ni < 4; ++ni) {
            int c2l = nw * 32 + ni * 8 + gc2;
            float b0 = __ldg(bp + c20 + c2l), b1 = __ldg(bp + c20 + c2l + 1);
            Cs[c2l * 132 + r]           = C[mi][ni][0] + b0;
            Cs[(c2l + 1) * 132 + r]     = C[mi][ni][1] + b1;
            Cs[c2l * 132 + r + 8]       = C[mi][ni][2] + b0;
            Cs[(c2l + 1) * 132 + r + 8] = C[mi][ni][3] + b1;
        }
    }
    __syncthreads();

    float* ob = out + (size_t)b * (C_DIM * N_DIM) + (size_t)c20 * N_DIM;
    const int f4 = tid & 31, sub = tid >> 5;
    #pragma unroll 4
    for (int i = 0; i < 64; ++i) {
        int rowid = i * 8 + sub;                   // 512 row-writes
        int c2l = rowid >> 3, mrep = rowid & 7;
        float4 v = *(float4*)&Cs[c2l * 132 + f4 * 4];
        *(float4*)(ob + (size_t)c2l * N_DIM + mrep * 128 + f4 * 4) = v;
    }
}

// ---------------------------------------------------------------------------
// Persistent fused kernel: 256 CTAs x 256 threads, 2 CTAs/SM (all resident).
// CTA i: Wp prep tile -> produce gemm1 tile (b=i>>3, n0=(i&7)*128) -> consume
// gemm2 tile (b=i>>3, c20=(i&7)*64). Producers never wait on consumers.
// ---------------------------------------------------------------------------
__global__ void __launch_bounds__(256, 2) fused_mma(const float* __restrict__ x,
                                                    const float* __restrict__ Wp,
                                                    const float* __restrict__ bp,
                                                    float* __restrict__ out) {
    extern __shared__ char smem[];
    const int bid = blockIdx.x, tid = threadIdx.x;
    const int b = bid >> 3, t8 = bid & 7;
    prep_wp_tile(Wp, smem, bid, tid);
    gemm1_body(x, smem, b, t8 * 128);
    gemm2_body(bp, out, smem, b, t8 * 64);
}

// ---------------------------------------------------------------------------
extern "C" void kernel_launch(void* const* d_in, const int* in_sizes, int n_in,
                              void* d_out, int out_size) {
    const float* x    = (const float*)d_in[0];
    const float* Wqkv = (const float*)d_in[1];
    const float* bqkv = (const float*)d_in[2];
    const float* Wp   = (const float*)d_in[3];
    const float* bp   = (const float*)d_in[4];
    float* out = (float*)d_out;

    cudaFuncSetAttribute(fused_mma, cudaFuncAttributeMaxDynamicSharedMemorySize, FUSED_SMEM);

    prep_wv<<<128, 256>>>(Wqkv, bqkv);
    fused_mma<<<256, 256, FUSED_SMEM>>>(x, Wp, bp, out);
}

// round 16
// speedup vs baseline: 1.3463x; 1.0341x over previous
#include <cuda_runtime.h>
#include <cuda_fp16.h>
#include <cstdint>

#define B_DIM 32
#define C_DIM 512
#define N_DIM 1024   // H*W

// ---------------- device scratch (allocation-free) --------------------------
__device__ __align__(16) unsigned short g_wv[64 * 512];     // Wv^T fp16 [d][c]
__device__ __align__(16) unsigned short g_wp[512 * 512];    // Wp^T fp16 [c2][c]
__device__ float g_bv[64];
__device__ __align__(16) unsigned g_v[B_DIM * 1024 * 32];   // v fp16 pairs [b][n][d/2]
__device__ int g_flag[B_DIM];                               // per-batch producer count

// ---------------- helpers ----------------------------------------------------
__device__ __forceinline__ unsigned smem_u32(const void* p) {
    unsigned a;
    asm("{ .reg .u64 t; cvta.to.shared.u64 t, %1; cvt.u32.u64 %0, t; }" : "=r"(a) : "l"(p));
    return a;
}
__device__ __forceinline__ void ldm_x4(unsigned* d, unsigned addr) {
    asm volatile("ldmatrix.sync.aligned.m8n8.x4.shared.b16 {%0,%1,%2,%3}, [%4];"
                 : "=r"(d[0]), "=r"(d[1]), "=r"(d[2]), "=r"(d[3]) : "r"(addr));
}
__device__ __forceinline__ void mma_f16(float* c, const unsigned* a, const unsigned* b) {
    asm volatile(
        "mma.sync.aligned.m16n8k16.row.col.f32.f16.f16.f32 "
        "{%0,%1,%2,%3}, {%4,%5,%6,%7}, {%8,%9}, {%0,%1,%2,%3};"
        : "+f"(c[0]), "+f"(c[1]), "+f"(c[2]), "+f"(c[3])
        : "r"(a[0]), "r"(a[1]), "r"(a[2]), "r"(a[3]), "r"(b[0]), "r"(b[1]));
}
__device__ __forceinline__ void cp16(unsigned dst, const void* src) {
    asm volatile("cp.async.cg.shared.global [%0], [%1], 16;" :: "r"(dst), "l"(src));
}
__device__ __forceinline__ void cp_commit() { asm volatile("cp.async.commit_group;" ::: "memory"); }
__device__ __forceinline__ void cp_wait0()  { asm volatile("cp.async.wait_group 0;" ::: "memory"); }
__device__ __forceinline__ void cp_wait1()  { asm volatile("cp.async.wait_group 1;" ::: "memory"); }

__device__ __forceinline__ unsigned cvt_f16x2(float f0, float f1) {
    unsigned h;
    asm("cvt.rn.f16x2.f32 %0, %1, %2;" : "=r"(h) : "f"(f1), "f"(f0));
    return h;
}

// stage layout (pitch 144B): A[128 rows] @0 (18432) | B[64 rows] @18432 (9216)
#define H_B   18432
#define H_STG 27648
#define FUSED_SMEM (3 * H_STG)   // 82944 -> still 2 CTAs/SM (<= 113664)

// ---------------------------------------------------------------------------
// prep (single launch, 288 blocks):
//   blocks [0,32)   -> Wv^T fp16 via 32x32 smem transpose (+bias, flags @bid 0)
//   blocks [32,288) -> Wp^T fp16 via 32x32 smem transpose
// ---------------------------------------------------------------------------
__global__ void prep_all(const float* __restrict__ Wqkv, const float* __restrict__ bqkv,
                         const float* __restrict__ Wp) {
    __shared__ float ts[32][33];
    int bid = blockIdx.x, tid = threadIdx.x;
    int tx = tid & 31, ty = tid >> 5;              // (32, 8)
    if (bid < 32) {
        if (bid == 0 && tid < B_DIM) g_flag[tid] = 0;
        if (bid == 0 && tid < 64) {
            float t = 0.f;
            #pragma unroll
            for (int h = 0; h < 8; ++h) t += bqkv[1024 + h * 64 + tid];
            g_bv[tid] = t * 0.125f;
        }
        // Wv tile: c0 x d0, load [c][d] coalesced, store [d][c] coalesced
        int c0 = (bid & 15) * 32, d0 = (bid >> 4) * 32;
        #pragma unroll
        for (int i = 0; i < 4; ++i) {
            int c = c0 + ty + i * 8;
            const float* p = Wqkv + (size_t)c * 1536 + 1024 + d0 + tx;
            float s = 0.f;
            #pragma unroll
            for (int h = 0; h < 8; ++h) s += p[h * 64];
            ts[ty + i * 8][tx] = s * 0.125f;
        }
        __syncthreads();
        #pragma unroll
        for (int i = 0; i < 4; ++i) {
            int d = d0 + ty + i * 8;
            __half hv = __float2half_rn(ts[tx][ty + i * 8]);
            g_wv[(size_t)d * 512 + c0 + tx] = *(unsigned short*)&hv;
        }
    } else {
        int t = bid - 32;                           // 256 tiles
        int c0 = (t & 15) * 32, c20 = (t >> 4) * 32;
        #pragma unroll
        for (int i = 0; i < 4; ++i) {
            int c = c0 + ty + i * 8;
            ts[ty + i * 8][tx] = Wp[(size_t)c * 512 + c20 + tx];
        }
        __syncthreads();
        #pragma unroll
        for (int i = 0; i < 4; ++i) {
            int c2 = c20 + ty + i * 8;
            __half hb = __float2half_rn(ts[tx][ty + i * 8]);
            g_wp[(size_t)c2 * 512 + c0 + tx] = *(unsigned short*)&hb;
        }
    }
}

// ---------------- warp MMA fragment offsets (pitch 144B) ---------------------
struct Frag { unsigned aoff[2]; unsigned boff[2]; };

__device__ __forceinline__ Frag make_frag(int lane, int mw, int nw) {
    Frag fr;
    const int j4 = lane >> 3, r8 = lane & 7;
    #pragma unroll
    for (int mi = 0; mi < 2; ++mi)
        fr.aoff[mi] = (mw * 32 + mi * 16 + (j4 & 1) * 8 + r8) * 144 + (j4 >> 1) * 16;
    const int g2 = (lane >> 4) & 1, c8 = (lane >> 3) & 1;
    #pragma unroll
    for (int j2 = 0; j2 < 2; ++j2)
        fr.boff[j2] = H_B + (nw * 32 + j2 * 16 + g2 * 8 + r8) * 144 + c8 * 16;
    return fr;
}

template<int K0, int K1>
__device__ __forceinline__ void mma_stage(unsigned base, const Frag& fr, float C[2][4][4]) {
    #pragma unroll
    for (int ks = K0; ks < K1; ++ks) {
        unsigned a[2][4], b[2][4];
        #pragma unroll
        for (int mi = 0; mi < 2; ++mi)
            ldm_x4(a[mi], base + fr.aoff[mi] + ks * 32);
        #pragma unroll
        for (int j2 = 0; j2 < 2; ++j2)
            ldm_x4(b[j2], base + fr.boff[j2] + ks * 32);
        #pragma unroll
        for (int mi = 0; mi < 2; ++mi)
            #pragma unroll
            for (int ni = 0; ni < 4; ++ni)
                mma_f16(C[mi][ni], a[mi], &b[ni >> 1][(ni & 1) * 2]);
    }
}

// -------------------- GEMM1 body: tile 128(n) x 64(d), K-chunk 64 x 8 -------
// (byte-identical to round-12 best config; uses stages 0 and 1 only)
__device__ __forceinline__ void gemm1_body(const float* __restrict__ x,
                                           char* smem, int b, int n0) {
    const int tid = threadIdx.x, lane = tid & 31, wid = tid >> 5;
    const int mw = wid >> 1, nw = wid & 1;
    const unsigned sb = smem_u32(smem);
    const Frag fr = make_frag(lane, mw, nw);

    const int m_ld = tid & 127, kb0 = tid >> 7;    // kblocks kb0 + 2i within half
    const float* xb = x + (size_t)b * (C_DIM * N_DIM) + n0;

    float C[2][4][4] = {};
    float f[2][8];

    auto ldg_half = [&](int kc, int h) {
        const float* xc = xb + (size_t)(kc * 64 + h * 32) * N_DIM;
        #pragma unroll
        for (int i = 0; i < 2; ++i) {
            int k0 = (kb0 + 2 * i) * 8;
            #pragma unroll
            for (int j = 0; j < 8; ++j)
                f[i][j] = xc[(size_t)(k0 + j) * N_DIM + m_ld];
        }
    };
    auto cvt_half = [&](int st, int h) {
        char* base = smem + st * H_STG;
        #pragma unroll
        for (int i = 0; i < 2; ++i) {
            unsigned w0 = cvt_f16x2(f[i][0], f[i][1]);
            unsigned w1 = cvt_f16x2(f[i][2], f[i][3]);
            unsigned w2 = cvt_f16x2(f[i][4], f[i][5]);
            unsigned w3 = cvt_f16x2(f[i][6], f[i][7]);
            unsigned off = m_ld * 144 + h * 64 + (kb0 + 2 * i) * 16;
            *(uint4*)(base + off) = make_uint4(w0, w1, w2, w3);
        }
    };
    auto issueB = [&](int kc, int st) {
        unsigned stb = sb + st * H_STG + H_B;
        #pragma unroll
        for (int i = 0; i < 2; ++i) {
            int idx = tid + i * 256;               // 512 quads: 64 rows x 8
            int r = idx >> 3, q = idx & 7;
            size_t s = (size_t)r * 512 + kc * 64 + q * 8;
            cp16(stb + r * 144 + q * 16, g_wv + s);
        }
        cp_commit();
    };

    // prologue: stage 0 = chunk 0 full; f = chunk 1 half 0
    ldg_half(0, 0);
    cvt_half(0, 0);
    ldg_half(0, 1);
    cvt_half(0, 1);
    ldg_half(1, 0);
    issueB(0, 0);

    for (int kc = 0; kc < 8; ++kc) {
        const int st = kc & 1, nst = st ^ 1;
        cp_wait0();
        __syncthreads();
        if (kc < 7) { cvt_half(nst, 0); issueB(kc + 1, nst); ldg_half(kc + 1, 1); }
        mma_stage<0, 2>(sb + st * H_STG, fr, C);
        if (kc < 7) { cvt_half(nst, 1); if (kc < 6) ldg_half(kc + 2, 0); }
        mma_stage<2, 4>(sb + st * H_STG, fr, C);
    }

    // epilogue: add bias, convert to fp16, store v
    const int gr = lane >> 2, gc2 = (lane & 3) * 2;
    #pragma unroll
    for (int mi = 0; mi < 2; ++mi) {
        int m = n0 + mw * 32 + mi * 16 + gr;
        unsigned base0 = (unsigned)(b * 1024 + m) * 32u;
        unsigned base1 = base0 + 8 * 32;
        #pragma unroll
        for (int ni = 0; ni < 4; ++ni) {
            int d = nw * 32 + ni * 8 + gc2;
            float bv0 = g_bv[d], bv1 = g_bv[d + 1];
            g_v[base0 + (d >> 1)] = cvt_f16x2(C[mi][ni][0] + bv0, C[mi][ni][1] + bv1);
            g_v[base1 + (d >> 1)] = cvt_f16x2(C[mi][ni][2] + bv0, C[mi][ni][3] + bv1);
        }
    }

    __threadfence();
    __syncthreads();
    if (tid == 0) atomicAdd(&g_flag[b], 1);
}

// -------------------- GEMM2 body: tile 128(r) x 64(c2), K-chunk 64 x 8 ------
// 3-stage cp.async ring, wait_group 1; Wp chunks 0-1 prefetched before spin.
__device__ __forceinline__ void gemm2_body(const float* __restrict__ bp,
                                           float* __restrict__ out,
                                           char* smem, int b, int c20) {
    const int tid = threadIdx.x, lane = tid & 31, wid = tid >> 5;
    const int mw = wid >> 1, nw = wid & 1;
    const unsigned sb = smem_u32(smem);
    const Frag fr = make_frag(lane, mw, nw);

    const unsigned short* vb = (const unsigned short*)g_v + (size_t)b * 65536;

    auto issueA = [&](int kc, int st) {
        unsigned stb = sb + st * H_STG;
        #pragma unroll
        for (int i = 0; i < 4; ++i) {
            int idx = tid + i * 256;               // 1024 quads (A: 128 rows x 8)
            int r = idx >> 3, q = idx & 7;
            cp16(stb + r * 144 + q * 16, vb + (size_t)r * 512 + kc * 64 + q * 8);
        }
    };
    auto issueB = [&](int kc, int st) {
        unsigned stb = sb + st * H_STG + H_B;
        #pragma unroll
        for (int i = 0; i < 2; ++i) {
            int idx = tid + i * 256;               // 512 quads (B: 64 rows x 8)
            int r = idx >> 3, q = idx & 7;
            cp16(stb + r * 144 + q * 16, g_wp + (size_t)(c20 + r) * 512 + kc * 64 + q * 8);
        }
    };

    // B prefetch (no dependency on v) hides the flag-spin
    issueB(0, 0);
    issueB(1, 1);
    cp_commit();                                   // G0 = {B0, B1}

    // acquire: wait for all 8 producer CTAs of this batch
    if (tid == 0) {
        volatile int* fl = &g_flag[b];
        while (*fl < 8) __nanosleep(64);
    }
    __syncthreads();
    __threadfence();

    issueA(0, 0); cp_commit();                     // G1 = {A0}
    issueA(1, 1); cp_commit();                     // G2 = {A1}

    float C[2][4][4] = {};

    for (int kc = 0; kc < 8; ++kc) {
        if (kc < 7) cp_wait1(); else cp_wait0();   // chunk kc's groups drained
        __syncthreads();                           // visibility + mma(kc-1) done
        if (kc < 6) {
            int nst = (kc + 2) % 3;
            issueA(kc + 2, nst);
            issueB(kc + 2, nst);
            cp_commit();                           // G(kc+3)
        }
        mma_stage<0, 4>(sb + (kc % 3) * H_STG, fr, C);
    }
    __syncthreads();

    // epilogue: stage to smem [c2][r] with bias, then coalesced x8 broadcast
    float* Cs = (float*)smem;      // [64][132] floats = 33792 B <= 82944
    const int gr = lane >> 2, gc2 = (lane & 3) * 2;
    #pragma unroll
    for (int mi = 0; mi < 2; ++mi) {
        int r = mw * 32 + mi * 16 + gr;
        #pragma unroll
        for (int ni = 0; ni < 4; ++ni) {
            int c2l = nw * 32 + ni * 8 + gc2;
            float b0 = __ldg(bp + c20 + c2l), b1 = __ldg(bp + c20 + c2l + 1);
            Cs[c2l * 132 + r]           = C[mi][ni][0] + b0;
            Cs[(c2l + 1) * 132 + r]     = C[mi][ni][1] + b1;
            Cs[c2l * 132 + r + 8]       = C[mi][ni][2] + b0;
            Cs[(c2l + 1) * 132 + r + 8] = C[mi][ni][3] + b1;
        }
    }
    __syncthreads();

    float* ob = out + (size_t)b * (C_DIM * N_DIM) + (size_t)c20 * N_DIM;
    const int f4 = tid & 31, sub = tid >> 5;
    #pragma unroll 4
    for (int i = 0; i < 64; ++i) {
        int rowid = i * 8 + sub;                   // 512 row-writes
        int c2l = rowid >> 3, mrep = rowid & 7;
        float4 v = *(float4*)&Cs[c2l * 132 + f4 * 4];
        *(float4*)(ob + (size_t)c2l * N_DIM + mrep * 128 + f4 * 4) = v;
    }
}

// ---------------------------------------------------------------------------
// Persistent fused kernel: 256 CTAs x 256 threads, 2 CTAs/SM (all resident).
// CTA i: produce gemm1 tile (b=i>>3, n0=(i&7)*128), then consume gemm2 tile
// (b=i>>3, c20=(i&7)*64). Producers never wait -> deadlock-free.
// ---------------------------------------------------------------------------
__global__ void __launch_bounds__(256, 2) fused_mma(const float* __restrict__ x,
                                                    const float* __restrict__ bp,
                                                    float* __restrict__ out) {
    extern __shared__ char smem[];
    const int bid = blockIdx.x;
    const int b = bid >> 3, t8 = bid & 7;
    gemm1_body(x, smem, b, t8 * 128);
    gemm2_body(bp, out, smem, b, t8 * 64);
}

// ---------------------------------------------------------------------------
extern "C" void kernel_launch(void* const* d_in, const int* in_sizes, int n_in,
                              void* d_out, int out_size) {
    const float* x    = (const float*)d_in[0];
    const float* Wqkv = (const float*)d_in[1];
    const float* bqkv = (const float*)d_in[2];
    const float* Wp   = (const float*)d_in[3];
    const float* bp   = (const float*)d_in[4];
    float* out = (float*)d_out;

    cudaFuncSetAttribute(fused_mma, cudaFuncAttributeMaxDynamicSharedMemorySize, FUSED_SMEM);

    prep_all<<<288, 256>>>(Wqkv, bqkv, Wp);
    fused_mma<<<256, 256, FUSED_SMEM>>>(x, bp, out);
}